// round 17
// baseline (speedup 1.0000x reference)
#include <cuda_runtime.h>

// Problem shape (fixed by the reference): (16, 1, 1024, 1024) fp32.
#define NB     16
#define HW     (1024 * 1024)
#define TOTAL  (NB * HW)
#define N4     (TOTAL / 4)
#define HW4    (HW / 4)          // 262144 float4 per batch

// ---------------------------------------------------------------------------
// helpers
// ---------------------------------------------------------------------------

// jnp.histogram bin over range (0,255), 256 bins, last edge inclusive.
// Monotone non-decreasing in v, so bin(min v)/bin(max v) give min/max bin.
__device__ __forceinline__ int bin_of(float v) {
    int b = (int)(v * (256.0f / 255.0f));
    return b > 255 ? 255 : b;
}

// Fast-path determination accumulator (branchless).
__device__ __forceinline__ void det_elem(float x, float& mnv, float& mxv,
                                         bool& anyv) {
    float v = x * 255.0f;                          // identical to reference mi
    bool inr = (v >= 0.0f) && (v <= 255.0f);
    mnv = fminf(mnv, inr ? v :  1e30f);
    mxv = fmaxf(mxv, inr ? v : -1e30f);
    anyv = anyv || (inr && (v == rintf(v)));       // rintf == jnp.round (half-even)
}

// Exact-path accumulator (fallback full scan).
__device__ __forceinline__ void acc_elem(float x, float& mnv, float& mxv,
                                         float& mnvv, float& mxvv) {
    float v = x * 255.0f;
    bool inr = (v >= 0.0f) && (v <= 255.0f);
    float r = rintf(v);
    bool val = inr && (v == r);
    if (inr) { mnv  = fminf(mnv,  v); mxv  = fmaxf(mxv,  v); }
    if (val) { mnvv = fminf(mnvv, v); mxvv = fmaxf(mxvv, v); }
}

__device__ __forceinline__ float warp_minf(float v) {
#pragma unroll
    for (int o = 16; o; o >>= 1) v = fminf(v, __shfl_xor_sync(0xffffffffu, v, o));
    return v;
}
__device__ __forceinline__ float warp_maxf(float v) {
#pragma unroll
    for (int o = 16; o; o >>= 1) v = fmaxf(v, __shfl_xor_sync(0xffffffffu, v, o));
    return v;
}

__device__ __forceinline__ void sm_pair(float ns, const float4& v,
                                        float4& p0, float4& p1) {
    {
        float e = __expf(fmaf(ns, v.x, 1.0f));
        float dd = __fdividef(1.0f, 1.0f + e);
        p0.x = dd; p1.x = 1.0f - dd;
    }
    {
        float e = __expf(fmaf(ns, v.y, 1.0f));
        float dd = __fdividef(1.0f, 1.0f + e);
        p0.y = dd; p1.y = 1.0f - dd;
    }
    {
        float e = __expf(fmaf(ns, v.z, 1.0f));
        float dd = __fdividef(1.0f, 1.0f + e);
        p0.z = dd; p1.z = 1.0f - dd;
    }
    {
        float e = __expf(fmaf(ns, v.w, 1.0f));
        float dd = __fdividef(1.0f, 1.0f + e);
        p0.w = dd; p1.w = 1.0f - dd;
    }
}

// ---------------------------------------------------------------------------
// Single fused kernel, WARP-INDEPENDENT flag determination (no __syncthreads).
//
// flag(batch) = 1 iff mask.max() > 0, where mask_output[r] = sum_j |r-j|*hist[j]:
//   - hist empty                   -> 0
//   - >= 2 distinct occupied bins  -> mask_output > 0 everywhere -> (any valid)
//   - exactly 1 occupied bin b0    -> zero only at r=b0 -> (valid idx != b0)
//
// Fast path: each thread checks its FIRST float4 (4 elements) for
// ">= 2 occupied bins AND >= 1 valid pixel"; __any_sync aggregates a warp's
// 128 elements of evidence. Both facts are monotone under adding data, so
// local evidence anywhere implies the global flag is 1. A warp that
// determines proceeds straight to compute+stores — no block-wide rendezvous,
// so one warp's slow loads can no longer delay the other warps' store issue
// (R16: block-wide BAR was the last structural coupling).
//
// Fallback (warp could not self-determine — only near-constant or integer-
// free images): THAT WARP performs an exact full scan of its batch with
// min/max tracking and a warp-level reduce, resolving all three cases
// exactly. Every warp of a batch computes the identical flag, so the output
// is consistent and correct for ANY input (just slow on adversarial data).
// No shared memory, no cross-warp or cross-kernel state at all.
//
//   m    = scale * v
//   out0 = 1/(1 + e^(1-2m)),  out1 = 1 - out0        (ns = -2*scale)
//
// ILP=4 front-batched LDG.128; stores .cs (128 MB evict-first write stream,
// measured ~4.9 TB/s — DRAM-write-bound; compute has large headroom).
// ---------------------------------------------------------------------------
__global__ void __launch_bounds__(256, 6) wsm_kernel(const float* __restrict__ irr,
                                                     float* __restrict__ out) {
    // Each block covers 1024 consecutive float4 (4 per thread, stride 256).
    // 256 blocks per batch -> batch = blockIdx.x >> 8.
    const int base = blockIdx.x * 1024 + threadIdx.x;
    const int b = blockIdx.x >> 8;

    const float4* __restrict__ in4 = reinterpret_cast<const float4*>(irr);
    float4* __restrict__ o0 = reinterpret_cast<float4*>(out);
    float4* __restrict__ o1 = reinterpret_cast<float4*>(out + (size_t)TOTAL);

    // front-batched loads (MLP_p1 = 4)
    float4 va = __ldg(&in4[base]);
    float4 vb = __ldg(&in4[base + 256]);
    float4 vc = __ldg(&in4[base + 512]);
    float4 vd = __ldg(&in4[base + 768]);

    // ---- flag determination from va only (4 elems/thread, 128/warp) ----
    int det;
    {
        float mnv = 1e30f, mxv = -1e30f;
        bool anyv = false;
        det_elem(va.x, mnv, mxv, anyv);
        det_elem(va.y, mnv, mxv, anyv);
        det_elem(va.z, mnv, mxv, anyv);
        det_elem(va.w, mnv, mxv, anyv);
        det = (mnv <= mxv) && anyv && (bin_of(mnv) != bin_of(mxv));
    }

    float ns;
    if (__any_sync(0xffffffffu, det)) {
        ns = -2.0f;                                  // flag = 1
    } else {
        // ---- fallback: this warp exactly scans its whole batch (rare) ----
        const float4* __restrict__ bat4 =
            reinterpret_cast<const float4*>(irr + (size_t)b * HW);
        const int lane = threadIdx.x & 31;
        float fmn = 1e30f, fmx = -1e30f;             // in-range v
        float gmn = 1e30f, gmx = -1e30f;             // valid v
        for (int i = lane; i < HW4; i += 32) {
            float4 v4 = bat4[i];
            acc_elem(v4.x, fmn, fmx, gmn, gmx);
            acc_elem(v4.y, fmn, fmx, gmn, gmx);
            acc_elem(v4.z, fmn, fmx, gmn, gmx);
            acc_elem(v4.w, fmn, fmx, gmn, gmx);
        }
        float a = warp_minf(fmn), bx = warp_maxf(fmx);
        float c = warp_minf(gmn), d = warp_maxf(gmx);
        int flag;
        const bool any_range = (a <= bx);
        const bool any_valid = (c <= d);
        if (!any_range) flag = 0;                            // hist empty
        else {
            int mnb = bin_of(a), mxb = bin_of(bx);
            if (mnb != mxb) flag = any_valid ? 1 : 0;        // >= 2 bins
            else {
                int mni = (int)c, mxi = (int)d;              // exact ints
                flag = (any_valid && (mni != mnb || mxi != mnb)) ? 1 : 0;
            }
        }
        ns = flag ? -2.0f : 0.0f;
    }

    // ---- output ----
    float4 a0, a1, b0, b1, c0, c1, d0, d1;
    sm_pair(ns, va, a0, a1);
    sm_pair(ns, vb, b0, b1);
    sm_pair(ns, vc, c0, c1);
    sm_pair(ns, vd, d0, d1);

    __stcs(&o0[base],       a0);
    __stcs(&o0[base + 256], b0);
    __stcs(&o0[base + 512], c0);
    __stcs(&o0[base + 768], d0);
    __stcs(&o1[base],       a1);
    __stcs(&o1[base + 256], b1);
    __stcs(&o1[base + 512], c1);
    __stcs(&o1[base + 768], d1);
}

// ---------------------------------------------------------------------------
// Launch. d_in[0] = image_irr (16M fp32), d_in[1] = image_vis (dead in the
// reference — never read). d_out = msks[0] then msks[1], concatenated.
// ---------------------------------------------------------------------------
extern "C" void kernel_launch(void* const* d_in, const int* in_sizes, int n_in,
                              void* d_out, int out_size) {
    const float* irr = (const float*)d_in[0];
    float* out = (float*)d_out;

    wsm_kernel<<<N4 / 1024, 256>>>(irr, out);
}